// round 1
// baseline (speedup 1.0000x reference)
#include <cuda_runtime.h>
#include <cuda_bf16.h>
#include <math_constants.h>

// SSDBoxHead: scores = softmax(cls_logits, axis=2); boxes = decode(bbox_pred, priors)
// Output layout: [scores (B*N*C floats)] ++ [boxes (B*N*4 floats)]

#define FULL_MASK 0xFFFFFFFFu

// ---------------------------------------------------------------------------
// Softmax over last dim C (C <= 96, specialized for C in (64, 96]).
// One warp per row. Lane l covers elements l, l+32, l+64 (predicated).
// ---------------------------------------------------------------------------
__global__ void softmax81_kernel(const float* __restrict__ in,
                                 float* __restrict__ out,
                                 long long rows, int C) {
    const int lane = threadIdx.x & 31;
    const long long warp_id =
        ((long long)blockIdx.x * blockDim.x + threadIdx.x) >> 5;
    const long long n_warps = ((long long)gridDim.x * blockDim.x) >> 5;

    for (long long r = warp_id; r < rows; r += n_warps) {
        const float* p = in + r * (long long)C;
        // C = 81: lane and lane+32 always in range; lane+64 only for lane < C-64.
        const bool has2 = (lane + 64) < C;
        float v0 = p[lane];
        float v1 = p[lane + 32];
        float v2 = has2 ? p[lane + 64] : -CUDART_INF_F;

        float m = fmaxf(fmaxf(v0, v1), v2);
        #pragma unroll
        for (int o = 16; o > 0; o >>= 1)
            m = fmaxf(m, __shfl_xor_sync(FULL_MASK, m, o));

        float e0 = __expf(v0 - m);
        float e1 = __expf(v1 - m);
        float e2 = has2 ? __expf(v2 - m) : 0.0f;

        float s = e0 + e1 + e2;
        #pragma unroll
        for (int o = 16; o > 0; o >>= 1)
            s += __shfl_xor_sync(FULL_MASK, s, o);

        const float inv = __frcp_rn(s);
        float* q = out + r * (long long)C;
        q[lane]      = e0 * inv;
        q[lane + 32] = e1 * inv;
        if (has2) q[lane + 64] = e2 * inv;
    }
}

// ---------------------------------------------------------------------------
// Box decode: thread per (b, n). float4 I/O. priors stay L2-resident (~0.4MB).
// centers = bp[:2]*0.1*prior[2:] + prior[:2]
// sizes   = exp(bp[2:]*0.2)*prior[2:]
// out     = [c - s/2, c + s/2]
// ---------------------------------------------------------------------------
__global__ void decode_kernel(const float4* __restrict__ bp,
                              const float4* __restrict__ priors,
                              float4* __restrict__ out,
                              int BN, int N) {
    int i = blockIdx.x * blockDim.x + threadIdx.x;
    if (i >= BN) return;

    float4 b = bp[i];
    int n = i % N;
    float4 pr = priors[n];

    float cx = fmaf(b.x * 0.1f, pr.z, pr.x);
    float cy = fmaf(b.y * 0.1f, pr.w, pr.y);
    float hw = 0.5f * __expf(b.z * 0.2f) * pr.z;
    float hh = 0.5f * __expf(b.w * 0.2f) * pr.w;

    out[i] = make_float4(cx - hw, cy - hh, cx + hw, cy + hh);
}

extern "C" void kernel_launch(void* const* d_in, const int* in_sizes, int n_in,
                              void* d_out, int out_size) {
    const float* cls_logits = (const float*)d_in[0];
    const float* bbox_pred  = (const float*)d_in[1];
    const float* priors     = (const float*)d_in[2];
    float* out = (float*)d_out;

    const long long cls_elems = in_sizes[0];       // B*N*C
    const long long bn4       = in_sizes[1];       // B*N*4
    const int N  = in_sizes[2] / 4;                // priors rows
    const int BN = (int)(bn4 / 4);                 // B*N
    const int C  = (int)(cls_elems / BN);          // 81
    const long long rows = BN;

    // --- softmax: warp per row ---
    {
        const int threads = 256;                   // 8 warps/block
        const long long warps_needed = rows;
        long long blocks = (warps_needed + 7) / 8;
        if (blocks > 0x7FFFFFFFLL) blocks = 0x7FFFFFFFLL;
        softmax81_kernel<<<(int)blocks, threads>>>(cls_logits, out, rows, C);
    }

    // --- decode boxes ---
    {
        float* boxes_out = out + cls_elems;        // 16B aligned (cls_elems % 4 == 0)
        const int threads = 256;
        const int blocks = (BN + threads - 1) / threads;
        decode_kernel<<<blocks, threads>>>((const float4*)bbox_pred,
                                           (const float4*)priors,
                                           (float4*)boxes_out, BN, N);
    }
}